// round 2
// baseline (speedup 1.0000x reference)
#include <cuda_runtime.h>
#include <cuda_fp16.h>
#include <cstdint>

// ======================= static device scratch (no allocs allowed) ==========
__device__ __align__(1024) __half g_xh[8192L * 4096];  // x in fp16
__device__ __align__(1024) __half g_qh[4096L * 4096];  // dequant Q fp16
__device__ __align__(1024) __half g_rh[256L * 4096];   // dequant R fp16
__device__ __align__(1024) __half g_lh[4096L * 256];   // dequant L fp16
__device__ __align__(1024) __half g_xr[8192L * 256];   // xr = x @ R^T (fp16)

// ======================= PTX helpers (sm_80-level only) =====================
__device__ __forceinline__ uint32_t smem_u32(const void* p) {
    return (uint32_t)__cvta_generic_to_shared(p);
}
__device__ __forceinline__ void cpa16(uint32_t s, const void* g) {
    asm volatile("cp.async.cg.shared.global [%0], [%1], 16;" :: "r"(s), "l"(g) : "memory");
}
#define CPA_COMMIT() asm volatile("cp.async.commit_group;" ::: "memory")
#define CPA_WAIT2()  asm volatile("cp.async.wait_group 2;" ::: "memory")

__device__ __forceinline__ void ldsm4(uint32_t& r0, uint32_t& r1, uint32_t& r2,
                                      uint32_t& r3, uint32_t addr) {
    asm volatile("ldmatrix.sync.aligned.m8n8.x4.shared.b16 {%0,%1,%2,%3}, [%4];"
                 : "=r"(r0), "=r"(r1), "=r"(r2), "=r"(r3) : "r"(addr));
}
__device__ __forceinline__ void mma16816(float* c, uint32_t a0, uint32_t a1,
                                         uint32_t a2, uint32_t a3,
                                         uint32_t b0, uint32_t b1) {
    asm volatile(
        "mma.sync.aligned.m16n8k16.row.col.f32.f16.f16.f32 "
        "{%0,%1,%2,%3}, {%4,%5,%6,%7}, {%8,%9}, {%0,%1,%2,%3};"
        : "+f"(c[0]), "+f"(c[1]), "+f"(c[2]), "+f"(c[3])
        : "r"(a0), "r"(a1), "r"(a2), "r"(a3), "r"(b0), "r"(b1));
}

// ======================= SMEM layout ========================================
// bias[128] floats at 0; 4 stages of (A 128x32 fp16 rows padded to 80B) +
// (B 128x32 fp16 rows padded to 80B).
static constexpr int ROWB       = 80;               // padded row bytes (conflict-free)
static constexpr int OFF_BIAS   = 0;
static constexpr int OFF_STAGES = 512;
static constexpr int A_BYTES    = 128 * ROWB;       // 10240
static constexpr int STAGE_BYTES = 2 * A_BYTES;     // 20480
static constexpr int SMEM_BYTES = OFF_STAGES + 4 * STAGE_BYTES;  // 82432

// ======================= GEMM kernel ========================================
// C[128,128] = A1@B1^T over k1c chunks, then += A2@B2^T over k2c chunks.
// A,B row-major fp16, K contiguous, chunk = 32 K. Output float(+bias) or half.
__global__ void __launch_bounds__(256, 1)
gemm_f16_kernel(const __half* __restrict__ A1, const __half* __restrict__ B1,
                int lda1, int ldb1, int k1c,
                const __half* __restrict__ A2, const __half* __restrict__ B2,
                int lda2, int ldb2, int k2c,
                const float* __restrict__ bias,
                float* __restrict__ outF, __half* __restrict__ outH, int ldo) {
    extern __shared__ char smem[];
    const int tid    = threadIdx.x;
    const int lane   = tid & 31;
    const int warp   = tid >> 5;
    const int warp_m = warp >> 2;          // 0..1  -> 64-row slab
    const int warp_n = warp & 3;           // 0..3  -> 32-col slab
    const int m0 = blockIdx.y * 128;
    const int n0 = blockIdx.x * 128;
    const uint32_t sb = smem_u32(smem);

    if (tid < 128)
        ((float*)(smem + OFF_BIAS))[tid] = bias ? bias[n0 + tid] : 0.0f;

    const int total = k1c + k2c;

    // ---- stage loader: 4x cp.async(16B) per thread (A:2, B:2) ----
    auto load_stage = [&](int kc) {
        const int buf = kc & 3;
        const uint32_t sa = sb + OFF_STAGES + buf * STAGE_BYTES;
        const uint32_t sbB = sa + A_BYTES;
        const __half* As; const __half* Bs; int lda, ldb, kk;
        if (kc < k1c) { As = A1; Bs = B1; lda = lda1; ldb = ldb1; kk = kc * 32; }
        else          { As = A2; Bs = B2; lda = lda2; ldb = ldb2; kk = (kc - k1c) * 32; }
#pragma unroll
        for (int i = 0; i < 2; i++) {
            int idx = tid + i * 256;           // 512 chunks of 16B
            int r = idx >> 2, c = idx & 3;
            cpa16(sa + r * ROWB + c * 16,
                  As + (size_t)(m0 + r) * lda + kk + c * 8);
        }
#pragma unroll
        for (int i = 0; i < 2; i++) {
            int idx = tid + i * 256;
            int r = idx >> 2, c = idx & 3;
            cpa16(sbB + r * ROWB + c * 16,
                  Bs + (size_t)(n0 + r) * ldb + kk + c * 8);
        }
    };

    float acc[4][4][4];
#pragma unroll
    for (int i = 0; i < 4; i++)
#pragma unroll
        for (int j = 0; j < 4; j++)
#pragma unroll
            for (int e = 0; e < 4; e++) acc[i][j][e] = 0.0f;

    // prologue: prefetch 3 stages
    for (int pc = 0; pc < 3; pc++) {
        if (pc < total) load_stage(pc);
        CPA_COMMIT();
    }

    // per-lane ldmatrix base offsets (within a stage buffer)
    const uint32_t a_lane = (uint32_t)((warp_m * 64 + (lane & 15)) * ROWB +
                                       (lane >> 4) * 16);
    const int bq = lane >> 3, br = lane & 7;
    const uint32_t b_lane = (uint32_t)((warp_n * 32 + ((bq >> 1) << 3) + br) * ROWB +
                                       (bq & 1) * 16);

    for (int kc = 0; kc < total; kc++) {
        CPA_WAIT2();
        __syncthreads();
        if (kc + 3 < total) load_stage(kc + 3);
        CPA_COMMIT();

        const int buf = kc & 3;
        const uint32_t sa = sb + OFF_STAGES + buf * STAGE_BYTES;
        const uint32_t sbB = sa + A_BYTES;

#pragma unroll
        for (int s = 0; s < 2; s++) {   // two k16 steps in the 32-K chunk
            uint32_t a[4][4];
#pragma unroll
            for (int mt = 0; mt < 4; mt++)
                ldsm4(a[mt][0], a[mt][1], a[mt][2], a[mt][3],
                      sa + a_lane + (uint32_t)(mt * 16 * ROWB + s * 32));
            uint32_t b[4][2];
#pragma unroll
            for (int nt2 = 0; nt2 < 2; nt2++)
                ldsm4(b[nt2 * 2][0], b[nt2 * 2][1], b[nt2 * 2 + 1][0], b[nt2 * 2 + 1][1],
                      sbB + b_lane + (uint32_t)(nt2 * 16 * ROWB + s * 32));
#pragma unroll
            for (int mt = 0; mt < 4; mt++)
#pragma unroll
                for (int nt = 0; nt < 4; nt++)
                    mma16816(acc[mt][nt], a[mt][0], a[mt][1], a[mt][2], a[mt][3],
                             b[nt][0], b[nt][1]);
        }
    }

    // ---- epilogue ----
    const int g  = lane >> 2;
    const int c2 = (lane & 3) * 2;
    const float* sbias = (const float*)(smem + OFF_BIAS);
#pragma unroll
    for (int mt = 0; mt < 4; mt++) {
#pragma unroll
        for (int h = 0; h < 2; h++) {
            const int row = m0 + warp_m * 64 + mt * 16 + g + h * 8;
#pragma unroll
            for (int nt = 0; nt < 4; nt++) {
                const int coll = warp_n * 32 + nt * 8 + c2;  // col within tile
                if (outF) {
                    float2 o;
                    o.x = acc[mt][nt][h * 2 + 0] + sbias[coll];
                    o.y = acc[mt][nt][h * 2 + 1] + sbias[coll + 1];
                    *(float2*)(outF + (size_t)row * ldo + n0 + coll) = o;
                } else {
                    __half2 o = __floats2half2_rn(acc[mt][nt][h * 2 + 0],
                                                  acc[mt][nt][h * 2 + 1]);
                    *(__half2*)(outH + (size_t)row * ldo + n0 + coll) = o;
                }
            }
        }
    }
}

// ======================= prologue kernels ===================================
__global__ void cvt_x_kernel(const float* __restrict__ x, __half* __restrict__ o, int n4) {
    int i = blockIdx.x * blockDim.x + threadIdx.x;
    if (i >= n4) return;
    float4 f = ((const float4*)x)[i];
    ((__half2*)o)[2 * i + 0] = __floats2half2_rn(f.x, f.y);
    ((__half2*)o)[2 * i + 1] = __floats2half2_rn(f.z, f.w);
}

// dequant int codes with group-128 scales; row length = 1<<kshift elements
__global__ void dequant_kernel(const int* __restrict__ v, const float* __restrict__ s,
                               __half* __restrict__ o, int n4, int kshift) {
    int i = blockIdx.x * blockDim.x + threadIdx.x;
    if (i >= n4) return;
    int4 q = ((const int4*)v)[i];
    int e0 = i << 2;
    int row = e0 >> kshift;
    int col = e0 & ((1 << kshift) - 1);
    float sc = s[(row << (kshift - 7)) + (col >> 7)];
    ((__half2*)o)[2 * i + 0] = __floats2half2_rn((float)q.x * sc, (float)q.y * sc);
    ((__half2*)o)[2 * i + 1] = __floats2half2_rn((float)q.z * sc, (float)q.w * sc);
}

// ======================= launch =============================================
extern "C" void kernel_launch(void* const* d_in, const int* in_sizes, int n_in,
                              void* d_out, int out_size) {
    const float* x    = (const float*)d_in[0];
    const int*   qv   = (const int*)d_in[1];
    const float* qs   = (const float*)d_in[2];
    const int*   lv   = (const int*)d_in[3];
    const float* ls   = (const float*)d_in[4];
    const int*   rv   = (const int*)d_in[5];
    const float* rs   = (const float*)d_in[6];
    const float* bias = (const float*)d_in[7];
    float* out = (float*)d_out;

    __half *xh, *qh, *rh, *lh, *xr;
    cudaGetSymbolAddress((void**)&xh, g_xh);
    cudaGetSymbolAddress((void**)&qh, g_qh);
    cudaGetSymbolAddress((void**)&rh, g_rh);
    cudaGetSymbolAddress((void**)&lh, g_lh);
    cudaGetSymbolAddress((void**)&xr, g_xr);

    cudaFuncSetAttribute(gemm_f16_kernel,
                         cudaFuncAttributeMaxDynamicSharedMemorySize, SMEM_BYTES);

    // prologue: fp16 convert + groupwise dequant
    {
        int n4 = 8192 * 4096 / 4;
        cvt_x_kernel<<<n4 / 256, 256>>>(x, xh, n4);
    }
    {
        int n4 = 4096 * 4096 / 4;
        dequant_kernel<<<n4 / 256, 256>>>(qv, qs, qh, n4, 12);
    }
    {
        int n4 = 256 * 4096 / 4;
        dequant_kernel<<<n4 / 256, 256>>>(rv, rs, rh, n4, 12);
    }
    {
        int n4 = 4096 * 256 / 4;
        dequant_kernel<<<n4 / 256, 256>>>(lv, ls, lh, n4, 8);
    }

    // xr = xh @ rh^T   (M=8192, N=256, K=4096) -> fp16
    gemm_f16_kernel<<<dim3(2, 64), 256, SMEM_BYTES>>>(
        xh, rh, 4096, 4096, 128,
        nullptr, nullptr, 0, 0, 0,
        nullptr, nullptr, xr, 256);

    // y = xh @ qh^T + xr @ lh^T + bias  (M=8192, N=4096; K=4096 then K=256)
    gemm_f16_kernel<<<dim3(32, 64), 256, SMEM_BYTES>>>(
        xh, qh, 4096, 4096, 128,
        xr, lh, 256, 256, 8,
        bias, out, nullptr, 4096);
}

// round 3
// speedup vs baseline: 1.2255x; 1.2255x over previous
#include <cuda_runtime.h>
#include <cuda_fp16.h>
#include <cstdint>

// ======================= static device scratch (no allocs allowed) ==========
__device__ __align__(1024) __half g_xh[8192L * 4096];  // x in fp16
__device__ __align__(1024) __half g_qh[4096L * 4096];  // dequant Q fp16
__device__ __align__(1024) __half g_rh[256L * 4096];   // dequant R fp16
__device__ __align__(1024) __half g_lh[4096L * 256];   // dequant L fp16
__device__ __align__(1024) __half g_xr[8192L * 256];   // xr = x @ R^T (fp16)

// ======================= PTX helpers (sm_80-level only) =====================
__device__ __forceinline__ uint32_t smem_u32(const void* p) {
    return (uint32_t)__cvta_generic_to_shared(p);
}
__device__ __forceinline__ void cpa16(uint32_t s, const void* g) {
    asm volatile("cp.async.cg.shared.global [%0], [%1], 16;" :: "r"(s), "l"(g) : "memory");
}
#define CPA_COMMIT() asm volatile("cp.async.commit_group;" ::: "memory")
#define CPA_WAIT2()  asm volatile("cp.async.wait_group 2;" ::: "memory")

__device__ __forceinline__ void ldsm4(uint32_t& r0, uint32_t& r1, uint32_t& r2,
                                      uint32_t& r3, uint32_t addr) {
    asm volatile("ldmatrix.sync.aligned.m8n8.x4.shared.b16 {%0,%1,%2,%3}, [%4];"
                 : "=r"(r0), "=r"(r1), "=r"(r2), "=r"(r3) : "r"(addr));
}
__device__ __forceinline__ void mma16816(float* c, uint32_t a0, uint32_t a1,
                                         uint32_t a2, uint32_t a3,
                                         uint32_t b0, uint32_t b1) {
    asm volatile(
        "mma.sync.aligned.m16n8k16.row.col.f32.f16.f16.f32 "
        "{%0,%1,%2,%3}, {%4,%5,%6,%7}, {%8,%9}, {%0,%1,%2,%3};"
        : "+f"(c[0]), "+f"(c[1]), "+f"(c[2]), "+f"(c[3])
        : "r"(a0), "r"(a1), "r"(a2), "r"(a3), "r"(b0), "r"(b1));
}

// ======================= SMEM layout ========================================
static constexpr int ROWB       = 80;     // padded row bytes (conflict-free ldsm)
static constexpr int OFF_BIAS   = 0;      // up to 256 floats
static constexpr int OFF_STAGES = 1024;
static constexpr int A_BYTES    = 128 * ROWB;  // 10240

// ======================= GEMM kernel ========================================
// C[128,NT] = A1@B1^T over k1c chunks, then += A2@B2^T over k2c chunks.
// A,B row-major fp16, K contiguous, chunk = 32 K. Output float(+bias) or half.
// 8 warps in 2x4 grid; warp tile = 64 x (NT/4).
template <int NT>
__global__ void __launch_bounds__(256)
gemm_f16_kernel(const __half* __restrict__ A1, const __half* __restrict__ B1,
                int lda1, int ldb1, int k1c,
                const __half* __restrict__ A2, const __half* __restrict__ B2,
                int lda2, int ldb2, int k2c,
                const float* __restrict__ bias,
                float* __restrict__ outF, __half* __restrict__ outH, int ldo) {
    constexpr int B_BYTES = NT * ROWB;
    constexpr int STAGE_BYTES = A_BYTES + B_BYTES;
    constexpr int NTN = NT / 4;     // warp n-tile
    constexpr int NCT = NTN / 8;    // 16n8 tiles per warp (4 or 8)

    extern __shared__ char smem[];
    const int tid    = threadIdx.x;
    const int lane   = tid & 31;
    const int warp   = tid >> 5;
    const int warp_m = warp >> 2;   // 0..1  -> 64-row slab
    const int warp_n = warp & 3;    // 0..3  -> NTN-col slab
    const int m0 = blockIdx.y * 128;
    const int n0 = blockIdx.x * NT;
    const uint32_t sb = smem_u32(smem);

    if (tid < NT)
        ((float*)(smem + OFF_BIAS))[tid] = bias ? bias[n0 + tid] : 0.0f;

    const int total = k1c + k2c;

    // ---- stage loader ----
    auto load_stage = [&](int kc) {
        const int buf = kc & 3;
        const uint32_t sa  = sb + OFF_STAGES + buf * STAGE_BYTES;
        const uint32_t sbB = sa + A_BYTES;
        const __half* As; const __half* Bs; int lda, ldb, kk;
        if (kc < k1c) { As = A1; Bs = B1; lda = lda1; ldb = ldb1; kk = kc * 32; }
        else          { As = A2; Bs = B2; lda = lda2; ldb = ldb2; kk = (kc - k1c) * 32; }
#pragma unroll
        for (int i = 0; i < 2; i++) {           // A: 512 chunks of 16B
            int idx = tid + i * 256;
            int r = idx >> 2, c = idx & 3;
            cpa16(sa + r * ROWB + c * 16,
                  As + (size_t)(m0 + r) * lda + kk + c * 8);
        }
#pragma unroll
        for (int i = 0; i < NT / 64; i++) {     // B: NT*4 chunks of 16B
            int idx = tid + i * 256;
            int r = idx >> 2, c = idx & 3;
            cpa16(sbB + r * ROWB + c * 16,
                  Bs + (size_t)(n0 + r) * ldb + kk + c * 8);
        }
    };

    float acc[4][NCT][4];
#pragma unroll
    for (int i = 0; i < 4; i++)
#pragma unroll
        for (int j = 0; j < NCT; j++)
#pragma unroll
            for (int e = 0; e < 4; e++) acc[i][j][e] = 0.0f;

    // prologue: prefetch 3 stages
    for (int pc = 0; pc < 3; pc++) {
        if (pc < total) load_stage(pc);
        CPA_COMMIT();
    }

    // per-lane ldmatrix base offsets (within a stage buffer)
    const uint32_t a_lane = (uint32_t)((warp_m * 64 + (lane & 15)) * ROWB +
                                       (lane >> 4) * 16);
    const int bq = lane >> 3, br = lane & 7;
    const uint32_t b_lane = (uint32_t)((warp_n * NTN + ((bq >> 1) << 3) + br) * ROWB +
                                       (bq & 1) * 16);

    for (int kc = 0; kc < total; kc++) {
        CPA_WAIT2();
        __syncthreads();
        if (kc + 3 < total) load_stage(kc + 3);
        CPA_COMMIT();

        const int buf = kc & 3;
        const uint32_t sa  = sb + OFF_STAGES + buf * STAGE_BYTES;
        const uint32_t sbB = sa + A_BYTES;

#pragma unroll
        for (int s = 0; s < 2; s++) {   // two k16 steps in the 32-K chunk
            uint32_t a[4][4];
#pragma unroll
            for (int mt = 0; mt < 4; mt++)
                ldsm4(a[mt][0], a[mt][1], a[mt][2], a[mt][3],
                      sa + a_lane + (uint32_t)(mt * 16 * ROWB + s * 32));
            uint32_t b[NCT][2];
#pragma unroll
            for (int nt2 = 0; nt2 < NCT / 2; nt2++)
                ldsm4(b[nt2 * 2][0], b[nt2 * 2][1], b[nt2 * 2 + 1][0], b[nt2 * 2 + 1][1],
                      sbB + b_lane + (uint32_t)(nt2 * 16 * ROWB + s * 32));
#pragma unroll
            for (int mt = 0; mt < 4; mt++)
#pragma unroll
                for (int nt = 0; nt < NCT; nt++)
                    mma16816(acc[mt][nt], a[mt][0], a[mt][1], a[mt][2], a[mt][3],
                             b[nt][0], b[nt][1]);
        }
    }

    // ---- epilogue ----
    const int g  = lane >> 2;
    const int c2 = (lane & 3) * 2;
    const float* sbias = (const float*)(smem + OFF_BIAS);
#pragma unroll
    for (int mt = 0; mt < 4; mt++) {
#pragma unroll
        for (int h = 0; h < 2; h++) {
            const int row = m0 + warp_m * 64 + mt * 16 + g + h * 8;
#pragma unroll
            for (int nt = 0; nt < NCT; nt++) {
                const int coll = warp_n * NTN + nt * 8 + c2;  // col within tile
                if (outF) {
                    float2 o;
                    o.x = acc[mt][nt][h * 2 + 0] + sbias[coll];
                    o.y = acc[mt][nt][h * 2 + 1] + sbias[coll + 1];
                    *(float2*)(outF + (size_t)row * ldo + n0 + coll) = o;
                } else {
                    __half2 o = __floats2half2_rn(acc[mt][nt][h * 2 + 0],
                                                  acc[mt][nt][h * 2 + 1]);
                    *(__half2*)(outH + (size_t)row * ldo + n0 + coll) = o;
                }
            }
        }
    }
}

// ======================= prologue kernels ===================================
__global__ void cvt_x_kernel(const float* __restrict__ x, __half* __restrict__ o, int n4) {
    int i = blockIdx.x * blockDim.x + threadIdx.x;
    if (i >= n4) return;
    float4 f = ((const float4*)x)[i];
    ((__half2*)o)[2 * i + 0] = __floats2half2_rn(f.x, f.y);
    ((__half2*)o)[2 * i + 1] = __floats2half2_rn(f.z, f.w);
}

// dequant int codes with group-128 scales; row length = 1<<kshift elements
__global__ void dequant_kernel(const int* __restrict__ v, const float* __restrict__ s,
                               __half* __restrict__ o, int n4, int kshift) {
    int i = blockIdx.x * blockDim.x + threadIdx.x;
    if (i >= n4) return;
    int4 q = ((const int4*)v)[i];
    int e0 = i << 2;
    int row = e0 >> kshift;
    int col = e0 & ((1 << kshift) - 1);
    float sc = s[(row << (kshift - 7)) + (col >> 7)];
    ((__half2*)o)[2 * i + 0] = __floats2half2_rn((float)q.x * sc, (float)q.y * sc);
    ((__half2*)o)[2 * i + 1] = __floats2half2_rn((float)q.z * sc, (float)q.w * sc);
}

// ======================= launch =============================================
extern "C" void kernel_launch(void* const* d_in, const int* in_sizes, int n_in,
                              void* d_out, int out_size) {
    const float* x    = (const float*)d_in[0];
    const int*   qv   = (const int*)d_in[1];
    const float* qs   = (const float*)d_in[2];
    const int*   lv   = (const int*)d_in[3];
    const float* ls   = (const float*)d_in[4];
    const int*   rv   = (const int*)d_in[5];
    const float* rs   = (const float*)d_in[6];
    const float* bias = (const float*)d_in[7];
    float* out = (float*)d_out;

    __half *xh, *qh, *rh, *lh, *xr;
    cudaGetSymbolAddress((void**)&xh, g_xh);
    cudaGetSymbolAddress((void**)&qh, g_qh);
    cudaGetSymbolAddress((void**)&rh, g_rh);
    cudaGetSymbolAddress((void**)&lh, g_lh);
    cudaGetSymbolAddress((void**)&xr, g_xr);

    constexpr int SMEM_128 = 1024 + 4 * (A_BYTES + 128 * ROWB);  // 82944
    constexpr int SMEM_256 = 1024 + 4 * (A_BYTES + 256 * ROWB);  // 123904
    cudaFuncSetAttribute(gemm_f16_kernel<128>,
                         cudaFuncAttributeMaxDynamicSharedMemorySize, SMEM_128);
    cudaFuncSetAttribute(gemm_f16_kernel<256>,
                         cudaFuncAttributeMaxDynamicSharedMemorySize, SMEM_256);

    // prologue: fp16 convert + groupwise dequant
    {
        int n4 = 8192 * 4096 / 4;
        cvt_x_kernel<<<n4 / 256, 256>>>(x, xh, n4);
    }
    {
        int n4 = 4096 * 4096 / 4;
        dequant_kernel<<<n4 / 256, 256>>>(qv, qs, qh, n4, 12);
    }
    {
        int n4 = 256 * 4096 / 4;
        dequant_kernel<<<n4 / 256, 256>>>(rv, rs, rh, n4, 12);
    }
    {
        int n4 = 4096 * 256 / 4;
        dequant_kernel<<<n4 / 256, 256>>>(lv, ls, lh, n4, 8);
    }

    // xr = xh @ rh^T   (M=8192, N=256, K=4096) -> fp16
    gemm_f16_kernel<128><<<dim3(2, 64), 256, SMEM_128>>>(
        xh, rh, 4096, 4096, 128,
        nullptr, nullptr, 0, 0, 0,
        nullptr, nullptr, xr, 256);

    // y = xh @ qh^T + xr @ lh^T + bias  (M=8192, N=4096; K=4096 then K=256)
    gemm_f16_kernel<256><<<dim3(16, 64), 256, SMEM_256>>>(
        xh, qh, 4096, 4096, 128,
        xr, lh, 256, 256, 8,
        bias, out, nullptr, 4096);
}

// round 4
// speedup vs baseline: 1.3750x; 1.1220x over previous
#include <cuda_runtime.h>
#include <cuda_fp16.h>
#include <cstdint>

// ======================= static device scratch (no allocs allowed) ==========
__device__ __align__(1024) __half g_xh[8192L * 4096];  // x in fp16
__device__ __align__(1024) __half g_qh[4096L * 4096];  // dequant Q, then Q + L@R
__device__ __align__(1024) __half g_rt[4096L * 256];   // dequant R, transposed [in, rank]
__device__ __align__(1024) __half g_lh[4096L * 256];   // dequant L fp16

// ======================= PTX helpers (sm_80-level only) =====================
__device__ __forceinline__ uint32_t smem_u32(const void* p) {
    return (uint32_t)__cvta_generic_to_shared(p);
}
__device__ __forceinline__ void cpa16(uint32_t s, const void* g) {
    asm volatile("cp.async.cg.shared.global [%0], [%1], 16;" :: "r"(s), "l"(g) : "memory");
}
#define CPA_COMMIT() asm volatile("cp.async.commit_group;" ::: "memory")
#define CPA_WAIT2()  asm volatile("cp.async.wait_group 2;" ::: "memory")

__device__ __forceinline__ void ldsm4(uint32_t& r0, uint32_t& r1, uint32_t& r2,
                                      uint32_t& r3, uint32_t addr) {
    asm volatile("ldmatrix.sync.aligned.m8n8.x4.shared.b16 {%0,%1,%2,%3}, [%4];"
                 : "=r"(r0), "=r"(r1), "=r"(r2), "=r"(r3) : "r"(addr));
}
__device__ __forceinline__ void mma16816(float* c, uint32_t a0, uint32_t a1,
                                         uint32_t a2, uint32_t a3,
                                         uint32_t b0, uint32_t b1) {
    asm volatile(
        "mma.sync.aligned.m16n8k16.row.col.f32.f16.f16.f32 "
        "{%0,%1,%2,%3}, {%4,%5,%6,%7}, {%8,%9}, {%0,%1,%2,%3};"
        : "+f"(c[0]), "+f"(c[1]), "+f"(c[2]), "+f"(c[3])
        : "r"(a0), "r"(a1), "r"(a2), "r"(a3), "r"(b0), "r"(b1));
}

// ======================= SMEM layout ========================================
static constexpr int ROWB       = 80;     // padded row bytes (conflict-free ldsm)
static constexpr int OFF_BIAS   = 0;      // up to 256 floats
static constexpr int OFF_STAGES = 1024;
static constexpr int A_BYTES    = 128 * ROWB;  // 10240

// ======================= GEMM kernel ========================================
// C[128,NT] = A@B^T over kc chunks of 32 K. A,B row-major fp16, K contiguous.
// Output: float(+bias) to outF, or half (optionally + addH) to outH.
// 8 warps in 2x4 grid; warp tile = 64 x (NT/4).
template <int NT>
__global__ void __launch_bounds__(256)
gemm_f16_kernel(const __half* __restrict__ A1, const __half* __restrict__ B1,
                int lda1, int ldb1, int k1c,
                const float* __restrict__ bias,
                float* __restrict__ outF, __half* __restrict__ outH,
                const __half* __restrict__ addH, int ldo) {
    constexpr int B_BYTES = NT * ROWB;
    constexpr int STAGE_BYTES = A_BYTES + B_BYTES;
    constexpr int NTN = NT / 4;     // warp n-tile
    constexpr int NCT = NTN / 8;    // 16n8 tiles per warp

    extern __shared__ char smem[];
    const int tid    = threadIdx.x;
    const int lane   = tid & 31;
    const int warp   = tid >> 5;
    const int warp_m = warp >> 2;   // 0..1  -> 64-row slab
    const int warp_n = warp & 3;    // 0..3  -> NTN-col slab
    const int m0 = blockIdx.y * 128;
    const int n0 = blockIdx.x * NT;
    const uint32_t sb = smem_u32(smem);

    if (tid < NT)
        ((float*)(smem + OFF_BIAS))[tid] = bias ? bias[n0 + tid] : 0.0f;

    const int total = k1c;

    // ---- stage loader ----
    auto load_stage = [&](int kc) {
        const int buf = kc & 3;
        const uint32_t sa  = sb + OFF_STAGES + buf * STAGE_BYTES;
        const uint32_t sbB = sa + A_BYTES;
        const int kk = kc * 32;
#pragma unroll
        for (int i = 0; i < 2; i++) {           // A: 512 chunks of 16B
            int idx = tid + i * 256;
            int r = idx >> 2, c = idx & 3;
            cpa16(sa + r * ROWB + c * 16,
                  A1 + (size_t)(m0 + r) * lda1 + kk + c * 8);
        }
#pragma unroll
        for (int i = 0; i < NT / 64; i++) {     // B: NT*4 chunks of 16B
            int idx = tid + i * 256;
            int r = idx >> 2, c = idx & 3;
            cpa16(sbB + r * ROWB + c * 16,
                  B1 + (size_t)(n0 + r) * ldb1 + kk + c * 8);
        }
    };

    float acc[4][NCT][4];
#pragma unroll
    for (int i = 0; i < 4; i++)
#pragma unroll
        for (int j = 0; j < NCT; j++)
#pragma unroll
            for (int e = 0; e < 4; e++) acc[i][j][e] = 0.0f;

    // prologue: prefetch 3 stages
    for (int pc = 0; pc < 3; pc++) {
        if (pc < total) load_stage(pc);
        CPA_COMMIT();
    }

    // per-lane ldmatrix base offsets (within a stage buffer)
    const uint32_t a_lane = (uint32_t)((warp_m * 64 + (lane & 15)) * ROWB +
                                       (lane >> 4) * 16);
    const int bq = lane >> 3, br = lane & 7;
    const uint32_t b_lane = (uint32_t)((warp_n * NTN + ((bq >> 1) << 3) + br) * ROWB +
                                       (bq & 1) * 16);

    for (int kc = 0; kc < total; kc++) {
        CPA_WAIT2();
        __syncthreads();
        if (kc + 3 < total) load_stage(kc + 3);
        CPA_COMMIT();

        const int buf = kc & 3;
        const uint32_t sa  = sb + OFF_STAGES + buf * STAGE_BYTES;
        const uint32_t sbB = sa + A_BYTES;

#pragma unroll
        for (int s = 0; s < 2; s++) {   // two k16 steps in the 32-K chunk
            uint32_t a[4][4];
#pragma unroll
            for (int mt = 0; mt < 4; mt++)
                ldsm4(a[mt][0], a[mt][1], a[mt][2], a[mt][3],
                      sa + a_lane + (uint32_t)(mt * 16 * ROWB + s * 32));
            uint32_t b[NCT][2];
#pragma unroll
            for (int nt2 = 0; nt2 < NCT / 2; nt2++)
                ldsm4(b[nt2 * 2][0], b[nt2 * 2][1], b[nt2 * 2 + 1][0], b[nt2 * 2 + 1][1],
                      sbB + b_lane + (uint32_t)(nt2 * 16 * ROWB + s * 32));
#pragma unroll
            for (int mt = 0; mt < 4; mt++)
#pragma unroll
                for (int nt = 0; nt < NCT; nt++)
                    mma16816(acc[mt][nt], a[mt][0], a[mt][1], a[mt][2], a[mt][3],
                             b[nt][0], b[nt][1]);
        }
    }

    // ---- epilogue ----
    const int g  = lane >> 2;
    const int c2 = (lane & 3) * 2;
    const float* sbias = (const float*)(smem + OFF_BIAS);
#pragma unroll
    for (int mt = 0; mt < 4; mt++) {
#pragma unroll
        for (int h = 0; h < 2; h++) {
            const int row = m0 + warp_m * 64 + mt * 16 + g + h * 8;
#pragma unroll
            for (int nt = 0; nt < NCT; nt++) {
                const int coll = warp_n * NTN + nt * 8 + c2;  // col within tile
                float v0 = acc[mt][nt][h * 2 + 0];
                float v1 = acc[mt][nt][h * 2 + 1];
                if (outF) {
                    float2 o;
                    o.x = v0 + sbias[coll];
                    o.y = v1 + sbias[coll + 1];
                    *(float2*)(outF + (size_t)row * ldo + n0 + coll) = o;
                } else {
                    if (addH) {
                        __half2 av = *(const __half2*)(addH + (size_t)row * ldo + n0 + coll);
                        v0 += __low2float(av);
                        v1 += __high2float(av);
                    }
                    *(__half2*)(outH + (size_t)row * ldo + n0 + coll) =
                        __floats2half2_rn(v0, v1);
                }
            }
        }
    }
}

// ======================= prologue kernels ===================================
__global__ void cvt_x_kernel(const float* __restrict__ x, __half* __restrict__ o, int n4) {
    int i = blockIdx.x * blockDim.x + threadIdx.x;
    if (i >= n4) return;
    float4 f = ((const float4*)x)[i];
    ((__half2*)o)[2 * i + 0] = __floats2half2_rn(f.x, f.y);
    ((__half2*)o)[2 * i + 1] = __floats2half2_rn(f.z, f.w);
}

// dequant int codes with group-128 scales; row length = 1<<kshift elements
__global__ void dequant_kernel(const int* __restrict__ v, const float* __restrict__ s,
                               __half* __restrict__ o, int n4, int kshift) {
    int i = blockIdx.x * blockDim.x + threadIdx.x;
    if (i >= n4) return;
    int4 q = ((const int4*)v)[i];
    int e0 = i << 2;
    int row = e0 >> kshift;
    int col = e0 & ((1 << kshift) - 1);
    float sc = s[(row << (kshift - 7)) + (col >> 7)];
    ((__half2*)o)[2 * i + 0] = __floats2half2_rn((float)q.x * sc, (float)q.y * sc);
    ((__half2*)o)[2 * i + 1] = __floats2half2_rn((float)q.z * sc, (float)q.w * sc);
}

// dequant + transpose R: v [256,4096] int codes, s [256,32] scales ->
// o [4096,256] fp16 (rank contiguous)
__global__ void dequant_r_t_kernel(const int* __restrict__ v,
                                   const float* __restrict__ s,
                                   __half* __restrict__ o) {
    __shared__ float tile[32][33];
    const int i0 = blockIdx.x * 32;  // in-dim block
    const int r0 = blockIdx.y * 32;  // rank block
    const int tx = threadIdx.x, ty = threadIdx.y;  // 32 x 8
#pragma unroll
    for (int j = 0; j < 4; j++) {
        int r = r0 + ty + j * 8;
        int i = i0 + tx;
        float sc = s[r * 32 + (i >> 7)];
        tile[ty + j * 8][tx] = (float)v[(size_t)r * 4096 + i] * sc;
    }
    __syncthreads();
#pragma unroll
    for (int j = 0; j < 4; j++) {
        int i = i0 + ty + j * 8;
        int r = r0 + tx;
        o[(size_t)i * 256 + r] = __float2half_rn(tile[tx][ty + j * 8]);
    }
}

// ======================= launch =============================================
extern "C" void kernel_launch(void* const* d_in, const int* in_sizes, int n_in,
                              void* d_out, int out_size) {
    const float* x    = (const float*)d_in[0];
    const int*   qv   = (const int*)d_in[1];
    const float* qs   = (const float*)d_in[2];
    const int*   lv   = (const int*)d_in[3];
    const float* ls   = (const float*)d_in[4];
    const int*   rv   = (const int*)d_in[5];
    const float* rs   = (const float*)d_in[6];
    const float* bias = (const float*)d_in[7];
    float* out = (float*)d_out;

    __half *xh, *qh, *rt, *lh;
    cudaGetSymbolAddress((void**)&xh, g_xh);
    cudaGetSymbolAddress((void**)&qh, g_qh);
    cudaGetSymbolAddress((void**)&rt, g_rt);
    cudaGetSymbolAddress((void**)&lh, g_lh);

    constexpr int SMEM_256 = 1024 + 4 * (A_BYTES + 256 * ROWB);  // 123904
    cudaFuncSetAttribute(gemm_f16_kernel<256>,
                         cudaFuncAttributeMaxDynamicSharedMemorySize, SMEM_256);

    // prologue: fp16 convert + groupwise dequant
    {
        int n4 = 8192 * 4096 / 4;
        cvt_x_kernel<<<n4 / 256, 256>>>(x, xh, n4);
    }
    {
        int n4 = 4096 * 4096 / 4;
        dequant_kernel<<<n4 / 256, 256>>>(qv, qs, qh, n4, 12);
    }
    {
        int n4 = 4096 * 256 / 4;
        dequant_kernel<<<n4 / 256, 256>>>(lv, ls, lh, n4, 8);
    }
    dequant_r_t_kernel<<<dim3(128, 8), dim3(32, 8)>>>(rv, rs, rt);

    // qh += lh @ rt^T  (M=4096, N=4096, K=256): Wc = Q + L@R, in fp16
    gemm_f16_kernel<256><<<dim3(16, 32), 256, SMEM_256>>>(
        lh, rt, 256, 256, 8,
        nullptr, nullptr, qh, qh, 4096);

    // y = xh @ Wc^T + bias  (M=8192, N=4096, K=4096)
    gemm_f16_kernel<256><<<dim3(16, 64), 256, SMEM_256>>>(
        xh, qh, 4096, 4096, 128,
        bias, out, nullptr, nullptr, 4096);
}

// round 5
// speedup vs baseline: 1.5655x; 1.1386x over previous
#include <cuda_runtime.h>
#include <cuda_fp16.h>
#include <cstdint>

// ======================= static device scratch (no allocs allowed) ==========
__device__ __align__(1024) __half g_xh[8192L * 4096];  // x in fp16
__device__ __align__(1024) __half g_qh[4096L * 4096];  // dequant Q, then Q + L@R
__device__ __align__(1024) __half g_rt[4096L * 256];   // dequant R, transposed [in, rank]
__device__ __align__(1024) __half g_lh[4096L * 256];   // dequant L fp16

// ======================= PTX helpers (sm_80-level only) =====================
__device__ __forceinline__ uint32_t smem_u32(const void* p) {
    return (uint32_t)__cvta_generic_to_shared(p);
}
__device__ __forceinline__ void cpa16(uint32_t s, const void* g) {
    asm volatile("cp.async.cg.shared.global [%0], [%1], 16;" :: "r"(s), "l"(g) : "memory");
}
#define CPA_COMMIT() asm volatile("cp.async.commit_group;" ::: "memory")
#define CPA_WAIT1()  asm volatile("cp.async.wait_group 1;" ::: "memory")

__device__ __forceinline__ void ldsm4(uint32_t& r0, uint32_t& r1, uint32_t& r2,
                                      uint32_t& r3, uint32_t addr) {
    asm volatile("ldmatrix.sync.aligned.m8n8.x4.shared.b16 {%0,%1,%2,%3}, [%4];"
                 : "=r"(r0), "=r"(r1), "=r"(r2), "=r"(r3) : "r"(addr));
}
__device__ __forceinline__ void mma16816(float* c, uint32_t a0, uint32_t a1,
                                         uint32_t a2, uint32_t a3,
                                         uint32_t b0, uint32_t b1) {
    asm volatile(
        "mma.sync.aligned.m16n8k16.row.col.f32.f16.f16.f32 "
        "{%0,%1,%2,%3}, {%4,%5,%6,%7}, {%8,%9}, {%0,%1,%2,%3};"
        : "+f"(c[0]), "+f"(c[1]), "+f"(c[2]), "+f"(c[3])
        : "r"(a0), "r"(a1), "r"(a2), "r"(a3), "r"(b0), "r"(b1));
}

// ======================= SMEM layout ========================================
static constexpr int ROWB       = 80;     // padded row bytes (conflict-free ldsm)
static constexpr int OFF_BIAS   = 0;      // 128 floats
static constexpr int OFF_STAGES = 1024;
static constexpr int A_BYTES    = 128 * ROWB;  // 10240
static constexpr int B_BYTES    = 128 * ROWB;  // 10240
static constexpr int STAGE_BYTES = A_BYTES + B_BYTES;           // 20480
static constexpr int SMEM_BYTES  = OFF_STAGES + 3 * STAGE_BYTES; // 62464

// ======================= GEMM kernel ========================================
// C[128,128] = A@B^T over kc chunks of 32 K. A,B row-major fp16, K contiguous.
// Output: float(+bias) to outF, or half (optionally + addH) to outH.
// 8 warps in 2x4 grid; warp tile = 64x32. 3-stage cp.async pipeline.
// __launch_bounds__(256,2): cap regs at 128 -> 2 CTAs/SM (smem 62.5KB x2 fits).
__global__ void __launch_bounds__(256, 2)
gemm_f16_kernel(const __half* __restrict__ A1, const __half* __restrict__ B1,
                int lda1, int ldb1, int k1c,
                const float* __restrict__ bias,
                float* __restrict__ outF, __half* __restrict__ outH,
                const __half* __restrict__ addH, int ldo) {
    extern __shared__ char smem[];
    const int tid    = threadIdx.x;
    const int lane   = tid & 31;
    const int warp   = tid >> 5;
    const int warp_m = warp >> 2;   // 0..1  -> 64-row slab
    const int warp_n = warp & 3;    // 0..3  -> 32-col slab
    const int m0 = blockIdx.y * 128;
    const int n0 = blockIdx.x * 128;
    const uint32_t sb = smem_u32(smem);

    if (tid < 128)
        ((float*)(smem + OFF_BIAS))[tid] = bias ? bias[n0 + tid] : 0.0f;

    const int total = k1c;

    // ---- stage loader: 4x cp.async(16B) per thread ----
    auto load_stage = [&](int kc, int buf) {
        const uint32_t sa  = sb + OFF_STAGES + buf * STAGE_BYTES;
        const uint32_t sbB = sa + A_BYTES;
        const int kk = kc * 32;
        {
            int r = tid >> 2, c = tid & 3;
            cpa16(sa + r * ROWB + c * 16,
                  A1 + (size_t)(m0 + r) * lda1 + kk + c * 8);
            int idx = tid + 256;
            int r2 = idx >> 2, c2 = idx & 3;
            cpa16(sa + r2 * ROWB + c2 * 16,
                  A1 + (size_t)(m0 + r2) * lda1 + kk + c2 * 8);
        }
        {
            int r = tid >> 2, c = tid & 3;
            cpa16(sbB + r * ROWB + c * 16,
                  B1 + (size_t)(n0 + r) * ldb1 + kk + c * 8);
            int idx = tid + 256;
            int r2 = idx >> 2, c2 = idx & 3;
            cpa16(sbB + r2 * ROWB + c2 * 16,
                  B1 + (size_t)(n0 + r2) * ldb1 + kk + c2 * 8);
        }
    };

    float acc[4][4][4];
#pragma unroll
    for (int i = 0; i < 4; i++)
#pragma unroll
        for (int j = 0; j < 4; j++)
#pragma unroll
            for (int e = 0; e < 4; e++) acc[i][j][e] = 0.0f;

    // prologue: prefetch 2 stages
    load_stage(0, 0);
    CPA_COMMIT();
    if (total > 1) load_stage(1, 1);
    CPA_COMMIT();

    // per-lane ldmatrix base offsets (within a stage buffer)
    const uint32_t a_lane = (uint32_t)((warp_m * 64 + (lane & 15)) * ROWB +
                                       (lane >> 4) * 16);
    const int bq = lane >> 3, br = lane & 7;
    const uint32_t b_lane = (uint32_t)((warp_n * 32 + ((bq >> 1) << 3) + br) * ROWB +
                                       (bq & 1) * 16);

    int buf = 0, nbuf = 2;  // buffer of kc, buffer for kc+2
    for (int kc = 0; kc < total; kc++) {
        CPA_WAIT1();
        __syncthreads();
        if (kc + 2 < total) load_stage(kc + 2, nbuf);
        CPA_COMMIT();

        const uint32_t sa  = sb + OFF_STAGES + buf * STAGE_BYTES;
        const uint32_t sbB = sa + A_BYTES;
        nbuf = buf;
        buf = (buf == 2) ? 0 : buf + 1;

#pragma unroll
        for (int s = 0; s < 2; s++) {   // two k16 steps in the 32-K chunk
            uint32_t a[4][4];
#pragma unroll
            for (int mt = 0; mt < 4; mt++)
                ldsm4(a[mt][0], a[mt][1], a[mt][2], a[mt][3],
                      sa + a_lane + (uint32_t)(mt * 16 * ROWB + s * 32));
            uint32_t b[4][2];
#pragma unroll
            for (int nt2 = 0; nt2 < 2; nt2++)
                ldsm4(b[nt2 * 2][0], b[nt2 * 2][1], b[nt2 * 2 + 1][0], b[nt2 * 2 + 1][1],
                      sbB + b_lane + (uint32_t)(nt2 * 16 * ROWB + s * 32));
#pragma unroll
            for (int mt = 0; mt < 4; mt++)
#pragma unroll
                for (int nt = 0; nt < 4; nt++)
                    mma16816(acc[mt][nt], a[mt][0], a[mt][1], a[mt][2], a[mt][3],
                             b[nt][0], b[nt][1]);
        }
    }

    // ---- epilogue ----
    const int g  = lane >> 2;
    const int c2 = (lane & 3) * 2;
    const float* sbias = (const float*)(smem + OFF_BIAS);
#pragma unroll
    for (int mt = 0; mt < 4; mt++) {
#pragma unroll
        for (int h = 0; h < 2; h++) {
            const int row = m0 + warp_m * 64 + mt * 16 + g + h * 8;
#pragma unroll
            for (int nt = 0; nt < 4; nt++) {
                const int coll = warp_n * 32 + nt * 8 + c2;  // col within tile
                float v0 = acc[mt][nt][h * 2 + 0];
                float v1 = acc[mt][nt][h * 2 + 1];
                if (outF) {
                    float2 o;
                    o.x = v0 + sbias[coll];
                    o.y = v1 + sbias[coll + 1];
                    *(float2*)(outF + (size_t)row * ldo + n0 + coll) = o;
                } else {
                    if (addH) {
                        __half2 av = *(const __half2*)(addH + (size_t)row * ldo + n0 + coll);
                        v0 += __low2float(av);
                        v1 += __high2float(av);
                    }
                    *(__half2*)(outH + (size_t)row * ldo + n0 + coll) =
                        __floats2half2_rn(v0, v1);
                }
            }
        }
    }
}

// ======================= prologue kernels ===================================
__global__ void cvt_x_kernel(const float* __restrict__ x, __half* __restrict__ o, int n4) {
    int i = blockIdx.x * blockDim.x + threadIdx.x;
    if (i >= n4) return;
    float4 f = ((const float4*)x)[i];
    ((__half2*)o)[2 * i + 0] = __floats2half2_rn(f.x, f.y);
    ((__half2*)o)[2 * i + 1] = __floats2half2_rn(f.z, f.w);
}

// dequant int codes with group-128 scales; row length = 1<<kshift elements
__global__ void dequant_kernel(const int* __restrict__ v, const float* __restrict__ s,
                               __half* __restrict__ o, int n4, int kshift) {
    int i = blockIdx.x * blockDim.x + threadIdx.x;
    if (i >= n4) return;
    int4 q = ((const int4*)v)[i];
    int e0 = i << 2;
    int row = e0 >> kshift;
    int col = e0 & ((1 << kshift) - 1);
    float sc = s[(row << (kshift - 7)) + (col >> 7)];
    ((__half2*)o)[2 * i + 0] = __floats2half2_rn((float)q.x * sc, (float)q.y * sc);
    ((__half2*)o)[2 * i + 1] = __floats2half2_rn((float)q.z * sc, (float)q.w * sc);
}

// dequant + transpose R: v [256,4096] int codes, s [256,32] scales ->
// o [4096,256] fp16 (rank contiguous)
__global__ void dequant_r_t_kernel(const int* __restrict__ v,
                                   const float* __restrict__ s,
                                   __half* __restrict__ o) {
    __shared__ float tile[32][33];
    const int i0 = blockIdx.x * 32;  // in-dim block
    const int r0 = blockIdx.y * 32;  // rank block
    const int tx = threadIdx.x, ty = threadIdx.y;  // 32 x 8
#pragma unroll
    for (int j = 0; j < 4; j++) {
        int r = r0 + ty + j * 8;
        int i = i0 + tx;
        float sc = s[r * 32 + (i >> 7)];
        tile[ty + j * 8][tx] = (float)v[(size_t)r * 4096 + i] * sc;
    }
    __syncthreads();
#pragma unroll
    for (int j = 0; j < 4; j++) {
        int i = i0 + ty + j * 8;
        int r = r0 + tx;
        o[(size_t)i * 256 + r] = __float2half_rn(tile[tx][ty + j * 8]);
    }
}

// ======================= launch =============================================
extern "C" void kernel_launch(void* const* d_in, const int* in_sizes, int n_in,
                              void* d_out, int out_size) {
    const float* x    = (const float*)d_in[0];
    const int*   qv   = (const int*)d_in[1];
    const float* qs   = (const float*)d_in[2];
    const int*   lv   = (const int*)d_in[3];
    const float* ls   = (const float*)d_in[4];
    const int*   rv   = (const int*)d_in[5];
    const float* rs   = (const float*)d_in[6];
    const float* bias = (const float*)d_in[7];
    float* out = (float*)d_out;

    __half *xh, *qh, *rt, *lh;
    cudaGetSymbolAddress((void**)&xh, g_xh);
    cudaGetSymbolAddress((void**)&qh, g_qh);
    cudaGetSymbolAddress((void**)&rt, g_rt);
    cudaGetSymbolAddress((void**)&lh, g_lh);

    cudaFuncSetAttribute(gemm_f16_kernel,
                         cudaFuncAttributeMaxDynamicSharedMemorySize, SMEM_BYTES);

    // prologue: fp16 convert + groupwise dequant
    {
        int n4 = 8192 * 4096 / 4;
        cvt_x_kernel<<<n4 / 256, 256>>>(x, xh, n4);
    }
    {
        int n4 = 4096 * 4096 / 4;
        dequant_kernel<<<n4 / 256, 256>>>(qv, qs, qh, n4, 12);
    }
    {
        int n4 = 4096 * 256 / 4;
        dequant_kernel<<<n4 / 256, 256>>>(lv, ls, lh, n4, 8);
    }
    dequant_r_t_kernel<<<dim3(128, 8), dim3(32, 8)>>>(rv, rs, rt);

    // qh += lh @ rt^T  (M=4096, N=4096, K=256): Wc = Q + L@R, in fp16
    gemm_f16_kernel<<<dim3(32, 32), 256, SMEM_BYTES>>>(
        lh, rt, 256, 256, 8,
        nullptr, nullptr, qh, qh, 4096);

    // y = xh @ Wc^T + bias  (M=8192, N=4096, K=4096)
    gemm_f16_kernel<<<dim3(32, 64), 256, SMEM_BYTES>>>(
        xh, qh, 4096, 4096, 128,
        bias, out, nullptr, nullptr, 4096);
}